// round 12
// baseline (speedup 1.0000x reference)
#include <cuda_runtime.h>

// Problem constants (shapes are fixed for this problem instance)
#define NMAX   16000
#define EMAX   48000
#define FMAX   32000
#define NGRAPH 32
#define NBUMP  32
#define NDIR   64
#define NHID   256
#define NCLS   10

// Scratch (device globals: allocation-free per harness rules)
static __device__ float g_nh[NMAX * NDIR];              // node heights [N][64]
static __device__ float g_diff[NGRAPH * NDIR * NBUMP];  // delta accum, layout [g][d][b]
static __device__ float g_hid[NGRAPH * NHID];           // MLP hidden layer
static __device__ int   g_cnt[64];                      // bucket counts: [0,32) edges, [32,64) faces
static __device__ int   g_cur[64];                      // bucket cursors (start offsets)
static __device__ unsigned g_perm[EMAX + FMAX];         // packed (g<<20)|item_idx

__device__ __forceinline__ float rcpa(float x) {
    float r;
    asm("rcp.approx.f32 %0, %1;" : "=f"(r) : "f"(x));
    return r;
}

__device__ __forceinline__ void red4(float* p, float a, float b, float c, float d) {
    asm volatile("red.global.add.v4.f32 [%0], {%1,%2,%3,%4};"
                 :: "l"(p), "f"(a), "f"(b), "f"(c), "f"(d) : "memory");
}

// Scatter the monotone sigmoid staircase of one (item, dir) as a difference
// array into base[b], b in [0,32), b contiguous. sigmoid(A + b*B) with
// A = -100*(1+h), B = 200/31. Band |z| < T evaluated; the "closing to 1" step
// emerges naturally because s saturates within e^-T inside the 8-slot window.
__device__ __forceinline__ void ecc_scatter(float h, float* base, float sgn) {
    const float Bc    = 6.4516129032f;      // 200/31
    const float invB  = 0.155f;             // 31/200
    const float T     = 10.0f;
    const float invEB = 0.00157827970f;     // exp(-200/31)

    float A = fmaf(h, -100.0f, -100.0f);    // z(b) = A + b*Bc
    if (A < -T - 31.0f * Bc) return;        // whole curve ~0: nothing to add

    int b0 = (int)ceilf((-T - A) * invB);  if (b0 < 0)  b0 = 0; if (b0 > 31) b0 = 31;
    int b1 = (int)floorf((T - A) * invB);  if (b1 > 31) b1 = 31;
    int w0 = b0 & ~3;                       // 16B-aligned window start

    // Evaluate sigmoid at all 8 window slots via e^{-z} recurrence.
    float q = __expf(-fmaf((float)w0, Bc, A));
    float v[8];
    float sprev = 0.0f;
    #pragma unroll
    for (int k = 0; k < 8; ++k) {
        float s = rcpa(1.0f + q);           // sigmoid = 1/(1+e^-z)
        v[k] = (s - sprev) * sgn;
        sprev = s;
        q *= invEB;
    }

    float* p = base + w0;
    red4(p, v[0], v[1], v[2], v[3]);
    if ((b1 + 1 - w0 >= 4) && (w0 <= 24))
        red4(p + 4, v[4], v[5], v[6], v[7]);
}

__global__ void k_zero() {
    g_diff[blockIdx.x * 256 + threadIdx.x] = 0.0f;
    if (blockIdx.x == 0 && threadIdx.x < 64) g_cnt[threadIdx.x] = 0;
}

// Node heights only (pure compute + coalesced store)
__global__ void k_nh(const float* __restrict__ x, const float* __restrict__ nw,
                     const float* __restrict__ v, int N) {
    int idx = blockIdx.x * blockDim.x + threadIdx.x;
    if (idx >= N * NDIR) return;
    int n = idx >> 6, d = idx & 63;
    float w = nw[n];
    g_nh[idx] = w * (x[3 * n]     * v[d] +
                     x[3 * n + 1] * v[NDIR + d] +
                     x[3 * n + 2] * v[2 * NDIR + d]);
}

// Histogram of edges/faces by graph (smem-aggregated)
__global__ void k_hist(const int* __restrict__ ei, const int* __restrict__ fc,
                       const int* __restrict__ bid, int E, int F) {
    __shared__ int h[64];
    if (threadIdx.x < 64) h[threadIdx.x] = 0;
    __syncthreads();
    int i = blockIdx.x * blockDim.x + threadIdx.x;
    if (i < E)            atomicAdd(&h[bid[ei[i]]], 1);
    else if (i < E + F)   atomicAdd(&h[32 + bid[fc[i - E]]], 1);
    __syncthreads();
    if (threadIdx.x < 64 && h[threadIdx.x]) atomicAdd(&g_cnt[threadIdx.x], h[threadIdx.x]);
}

// Exclusive scan of 64 bucket counts -> cursors. Edge region [0,E), face [E,E+F).
__global__ void k_scan(int E) {
    if (threadIdx.x == 0) {
        int s = 0;
        for (int k = 0; k < 32; ++k) { g_cur[k] = s; s += g_cnt[k]; }
        s = E;
        for (int k = 32; k < 64; ++k) { g_cur[k] = s; s += g_cnt[k]; }
    }
}

// Scatter item indices into graph buckets, packed with g
__global__ void k_bucket(const int* __restrict__ ei, const int* __restrict__ fc,
                         const int* __restrict__ bid, int E, int F) {
    int i = blockIdx.x * blockDim.x + threadIdx.x;
    if (i < E) {
        int g = bid[ei[i]];
        int pos = atomicAdd(&g_cur[g], 1);
        g_perm[pos] = ((unsigned)g << 20) | (unsigned)i;
    } else if (i < E + F) {
        int j = i - E;
        int g = bid[fc[j]];
        int pos = atomicAdd(&g_cur[32 + g], 1);
        g_perm[pos] = ((unsigned)g << 20) | (unsigned)j;
    }
}

// Unified ECC scatter: items [0,N) nodes, [N,N+E) edges, [N+E,N+E+F) faces.
// Warp = 4 consecutive items (same graph after sort) x 8 dirs:
// REDs from lanes with equal local_d hit the SAME [g][d] 128B line.
__global__ void k_ecc(const float* __restrict__ ew, const float* __restrict__ fw,
                      const int* __restrict__ ei, const int* __restrict__ fc,
                      const int* __restrict__ bid, int N, int E, int F) {
    int tid = threadIdx.x;
    int item = blockIdx.x * 4 + ((tid >> 3) & 3);
    int d = (tid >> 5) * 8 + (tid & 7);

    float h, sgn;
    int g;
    if (item < N) {                          // node
        g = bid[item];
        h = g_nh[(item << 6) + d];
        sgn = 1.0f;
    } else if (item < N + E) {               // edge
        unsigned q = g_perm[item - N];
        g = q >> 20;
        int e = q & 0xFFFFF;
        int a = ei[e], b = ei[E + e];
        h = fmaxf(g_nh[(a << 6) + d], g_nh[(b << 6) + d]) * ew[e];
        sgn = -1.0f;
    } else {                                 // face
        unsigned q = g_perm[item - N];       // face region starts at perm[E]
        g = q >> 20;
        int f = q & 0xFFFFF;
        int a = fc[f], b = fc[F + f], c = fc[2 * F + f];
        h = fmaxf(fmaxf(g_nh[(a << 6) + d], g_nh[(b << 6) + d]),
                  g_nh[(c << 6) + d]) * fw[f];
        sgn = 1.0f;
    }
    ecc_scatter(h, &g_diff[(g << 11) + (d << 5)], sgn);
}

// Prefix-sum deltas over b: g_diff[g][d][b] -> flat[g][b*64+d]
__global__ void k_prefix(float* __restrict__ flat) {
    int idx = blockIdx.x * 256 + threadIdx.x;   // 0..2047 : (g, d)
    int g = idx >> 6, d = idx & 63;
    const float* src = &g_diff[(g << 11) + (d << 5)];
    float* dst = flat + (g << 11) + d;
    float s = 0.0f;
    #pragma unroll
    for (int b = 0; b < NBUMP; ++b) {
        s += src[b];
        dst[b << 6] = s;
    }
}

// hidden = relu(flat @ W1.T + b1): one warp per (g, hid), float4 dot of 2048
__global__ void k_hidden(const float* __restrict__ flat, const float* __restrict__ W1,
                         const float* __restrict__ b1) {
    int t = blockIdx.x * blockDim.x + threadIdx.x;
    int warp = t >> 5, lane = t & 31;           // 8192 warps total
    int g = warp >> 8, hid = warp & 255;
    const float4* fr = (const float4*)(flat + (g << 11));
    const float4* wr = (const float4*)(W1 + hid * 2048);
    float s = 0.0f;
    #pragma unroll
    for (int k = lane; k < 512; k += 32) {
        float4 a = fr[k], w = wr[k];
        s += a.x * w.x + a.y * w.y + a.z * w.z + a.w * w.w;
    }
    #pragma unroll
    for (int o = 16; o; o >>= 1) s += __shfl_xor_sync(0xffffffffu, s, o);
    if (lane == 0) g_hid[(g << 8) + hid] = fmaxf(s + b1[hid], 0.0f);
}

// logits = hidden @ W2.T + b2: one warp per (g, class)
__global__ void k_logits(const float* __restrict__ W2, const float* __restrict__ b2,
                         float* __restrict__ out) {
    int t = blockIdx.x * blockDim.x + threadIdx.x;
    int warp = t >> 5, lane = t & 31;
    if (warp >= NGRAPH * NCLS) return;
    int g = warp / NCLS, c = warp - g * NCLS;
    const float* hr = g_hid + (g << 8);
    const float* wr = W2 + (c << 8);
    float s = 0.0f;
    #pragma unroll
    for (int k = lane; k < NHID; k += 32) s += hr[k] * wr[k];
    #pragma unroll
    for (int o = 16; o; o >>= 1) s += __shfl_xor_sync(0xffffffffu, s, o);
    if (lane == 0) out[g * NCLS + c] = s + b2[c];
}

extern "C" void kernel_launch(void* const* d_in, const int* in_sizes, int n_in,
                              void* d_out, int out_size) {
    const float* x  = (const float*)d_in[0];
    const float* nw = (const float*)d_in[1];
    const float* ew = (const float*)d_in[2];
    const float* fw = (const float*)d_in[3];
    const float* v  = (const float*)d_in[4];
    const float* W1 = (const float*)d_in[5];
    const float* b1 = (const float*)d_in[6];
    const float* W2 = (const float*)d_in[7];
    const float* b2 = (const float*)d_in[8];
    const int*   ei = (const int*)d_in[9];   // edge_index [2,E] (int32)
    const int*   fc = (const int*)d_in[10];  // face [3,F]
    const int*   bid= (const int*)d_in[11];  // batch_ids [N]

    int N = in_sizes[1];   // node_weights count
    int E = in_sizes[2];   // edge_weights count
    int F = in_sizes[3];   // face_weights count

    float* out  = (float*)d_out;           // [0, 320): logits
    float* flat = out + NGRAPH * NCLS;     // [320, 320+65536): flat ECC

    k_zero<<<(NGRAPH * NBUMP * NDIR) / 256, 256>>>();
    k_hist<<<(E + F + 255) / 256, 256>>>(ei, fc, bid, E, F);
    k_scan<<<1, 32>>>(E);
    k_bucket<<<(E + F + 255) / 256, 256>>>(ei, fc, bid, E, F);
    k_nh<<<(N * NDIR + 255) / 256, 256>>>(x, nw, v, N);
    k_ecc<<<(N + E + F) / 4, 256>>>(ew, fw, ei, fc, bid, N, E, F);
    k_prefix<<<8, 256>>>(flat);
    k_hidden<<<1024, 256>>>(flat, W1, b1);
    k_logits<<<(NGRAPH * NCLS * 32 + 255) / 256, 256>>>(W2, b2, out);
}

// round 13
// speedup vs baseline: 1.6315x; 1.6315x over previous
#include <cuda_runtime.h>

// Problem constants (shapes are fixed for this problem instance)
#define NMAX   16000
#define EMAX   48000
#define FMAX   32000
#define NGRAPH 32
#define NBUMP  32
#define NDIR   64
#define NHID   256
#define NCLS   10

#define SORT_BLOCKS  64
#define SORT_THREADS 256

#define ECC_L     48                 // items per thread-run
#define ECC_ITEMS 192                // 4 runs * 48 items per block
#define ACC_PAD   33                 // bank-conflict-free column stride

// Scratch (device globals: allocation-free per harness rules)
static __device__ float g_nh[NMAX * NDIR];              // node heights [N][64]
static __device__ float g_diff[NGRAPH * NDIR * NBUMP];  // delta accum, layout [g][d][b]
static __device__ float g_hid[NGRAPH * NHID];           // MLP hidden layer
static __device__ int   g_bcnt[SORT_BLOCKS * 64];       // per-block bucket counts
static __device__ int   g_boff[SORT_BLOCKS * 64];       // per-block bucket offsets
static __device__ unsigned g_perm[EMAX + FMAX];         // packed (g<<20)|item_idx

__device__ __forceinline__ float rcpa(float x) {
    float r;
    asm("rcp.approx.f32 %0, %1;" : "=f"(r) : "f"(x));
    return r;
}

__device__ __forceinline__ void red4(float* p, float a, float b, float c, float d) {
    asm volatile("red.global.add.v4.f32 [%0], {%1,%2,%3,%4};"
                 :: "l"(p), "f"(a), "f"(b), "f"(c), "f"(d) : "memory");
}

__global__ void k_zero() {
    g_diff[blockIdx.x * 256 + threadIdx.x] = 0.0f;
}

// ---------- counting sort of edges+faces by graph (no global contention) ----------

// Pass A: per-block smem histogram -> g_bcnt (plain stores, no global atomics)
__global__ void k_count(const int* __restrict__ ei, const int* __restrict__ fc,
                        const int* __restrict__ bid, int E, int F) {
    __shared__ int h[64];
    if (threadIdx.x < 64) h[threadIdx.x] = 0;
    __syncthreads();
    for (int i = blockIdx.x * SORT_THREADS + threadIdx.x; i < E + F;
         i += SORT_BLOCKS * SORT_THREADS) {
        int bkt = (i < E) ? bid[ei[i]] : (32 + bid[fc[i - E]]);
        atomicAdd(&h[bkt], 1);
    }
    __syncthreads();
    if (threadIdx.x < 64) g_bcnt[blockIdx.x * 64 + threadIdx.x] = h[threadIdx.x];
}

// Pass B: offsets. Thread b scans its bucket across blocks. Edge buckets [0,32)
// start at 0; face buckets [32,64) start at E.
__global__ void k_offsets(int E) {
    __shared__ int tot[64], base[64];
    int b = threadIdx.x;                      // 64 threads
    int s = 0;
    for (int k = 0; k < SORT_BLOCKS; ++k) s += g_bcnt[k * 64 + b];
    tot[b] = s;
    __syncthreads();
    if (b == 0) {
        int a = 0;
        for (int k = 0; k < 32; ++k)  { base[k] = a; a += tot[k]; }
        a = E;
        for (int k = 32; k < 64; ++k) { base[k] = a; a += tot[k]; }
    }
    __syncthreads();
    int run = base[b];
    for (int k = 0; k < SORT_BLOCKS; ++k) { g_boff[k * 64 + b] = run; run += g_bcnt[k * 64 + b]; }
}

// Pass C: scatter with per-block smem cursors
__global__ void k_scatter(const int* __restrict__ ei, const int* __restrict__ fc,
                          const int* __restrict__ bid, int E, int F) {
    __shared__ int cur[64];
    if (threadIdx.x < 64) cur[threadIdx.x] = g_boff[blockIdx.x * 64 + threadIdx.x];
    __syncthreads();
    for (int i = blockIdx.x * SORT_THREADS + threadIdx.x; i < E + F;
         i += SORT_BLOCKS * SORT_THREADS) {
        int g, idx, bkt;
        if (i < E) { idx = i;     g = bid[ei[i]];     bkt = g; }
        else       { idx = i - E; g = bid[fc[i - E]]; bkt = 32 + g; }
        int pos = atomicAdd(&cur[bkt], 1);
        g_perm[pos] = ((unsigned)g << 20) | (unsigned)idx;
    }
}

// ---------- node heights ----------
__global__ void k_nh(const float* __restrict__ x, const float* __restrict__ nw,
                     const float* __restrict__ v, int N) {
    int idx = blockIdx.x * blockDim.x + threadIdx.x;
    if (idx >= N * NDIR) return;
    int n = idx >> 6, d = idx & 63;
    float w = nw[n];
    g_nh[idx] = w * (x[3 * n]     * v[d] +
                     x[3 * n + 1] * v[NDIR + d] +
                     x[3 * n + 2] * v[2 * NDIR + d]);
}

// ---------- unified ECC with per-thread smem accumulators ----------

__device__ __forceinline__ void flushacc(const float* a, int g, int d) {
    float* p = &g_diff[(g << 11) + (d << 5)];
    #pragma unroll
    for (int q = 0; q < 8; ++q)
        red4(p + q * 4, a[q * 4], a[q * 4 + 1], a[q * 4 + 2], a[q * 4 + 3]);
}

// Items: [0,N) nodes (+), [N,N+E) edges (-) via perm, [N+E,N+E+F) faces (+) via perm.
// Thread = (dir d = tid&63, run c = tid>>6). Each thread owns a private 32-bin
// smem column (pad 33 -> bank = (lane + b) & 31, conflict-free) and flushes to
// g_diff with v4 REDs only on graph change / end. Items are graph-sorted, so
// flushes are rare (~1 per thread).
__global__ void k_ecc(const float* __restrict__ ew, const float* __restrict__ fw,
                      const int* __restrict__ ei, const int* __restrict__ fc,
                      const int* __restrict__ bid, int N, int E, int F) {
    __shared__ float acc[256 * ACC_PAD];
    int t = threadIdx.x;
    int d = t & 63;
    float* a = &acc[t * ACC_PAD];
    #pragma unroll
    for (int b = 0; b < 32; ++b) a[b] = 0.0f;

    int M = N + E + F;
    int i0 = blockIdx.x * ECC_ITEMS + (t >> 6) * ECC_L;
    int i1 = min(i0 + ECC_L, M);
    int curg = -1;

    const float Bc    = 6.4516129032f;      // 200/31
    const float invB  = 0.155f;             // 31/200
    const float T     = 10.0f;
    const float invEB = 0.00157827970f;     // exp(-200/31)

    for (int i = i0; i < i1; ++i) {
        int g; float h, sgn;
        if (i < N) {                         // node
            g = bid[i];
            h = g_nh[(i << 6) + d];
            sgn = 1.0f;
        } else {
            unsigned p = g_perm[i - N];
            g = p >> 20;
            int e = p & 0xFFFFF;
            if (i < N + E) {                 // edge
                int u = ei[e], w = ei[E + e];
                h = fmaxf(g_nh[(u << 6) + d], g_nh[(w << 6) + d]) * ew[e];
                sgn = -1.0f;
            } else {                         // face
                int u = fc[e], w = fc[F + e], y = fc[2 * F + e];
                h = fmaxf(fmaxf(g_nh[(u << 6) + d], g_nh[(w << 6) + d]),
                          g_nh[(y << 6) + d]) * fw[e];
                sgn = 1.0f;
            }
        }
        if (g != curg) {                     // warp-uniform branch (same item)
            if (curg >= 0) {
                flushacc(a, curg, d);
                #pragma unroll
                for (int b = 0; b < 32; ++b) a[b] = 0.0f;
            }
            curg = g;
        }
        // monotone sigmoid staircase as difference array, band |z| < T
        float A = fmaf(h, -100.0f, -100.0f);   // z(b) = A + b*Bc
        if (A < -T - 31.0f * Bc) continue;     // whole curve ~0
        int b0 = (int)ceilf((-T - A) * invB);
        b0 = max(b0, 0); b0 = min(b0, 31);
        int b1 = (int)floorf((T - A) * invB);
        b1 = min(b1, 31);
        float q = __expf(-fmaf((float)b0, Bc, A));
        float sprev = 0.0f;
        for (int b = b0; b <= b1; ++b) {
            float s = rcpa(1.0f + q);          // sigmoid = 1/(1+e^-z)
            a[b] += (s - sprev) * sgn;
            sprev = s;
            q *= invEB;
        }
        int bx = max(b1 + 1, 0);               // closing step to all-ones tail
        if (bx <= 31) a[bx] += (1.0f - sprev) * sgn;
    }
    if (curg >= 0) flushacc(a, curg, d);
}

// Prefix-sum deltas over b: g_diff[g][d][b] -> flat[g][b*64+d]
__global__ void k_prefix(float* __restrict__ flat) {
    int idx = blockIdx.x * 256 + threadIdx.x;   // 0..2047 : (g, d)
    int g = idx >> 6, d = idx & 63;
    const float* src = &g_diff[(g << 11) + (d << 5)];
    float* dst = flat + (g << 11) + d;
    float s = 0.0f;
    #pragma unroll
    for (int b = 0; b < NBUMP; ++b) {
        s += src[b];
        dst[b << 6] = s;
    }
}

// hidden = relu(flat @ W1.T + b1): one warp per (g, hid), float4 dot of 2048
__global__ void k_hidden(const float* __restrict__ flat, const float* __restrict__ W1,
                         const float* __restrict__ b1) {
    int t = blockIdx.x * blockDim.x + threadIdx.x;
    int warp = t >> 5, lane = t & 31;           // 8192 warps total
    int g = warp >> 8, hid = warp & 255;
    const float4* fr = (const float4*)(flat + (g << 11));
    const float4* wr = (const float4*)(W1 + hid * 2048);
    float s = 0.0f;
    #pragma unroll
    for (int k = lane; k < 512; k += 32) {
        float4 a = fr[k], w = wr[k];
        s += a.x * w.x + a.y * w.y + a.z * w.z + a.w * w.w;
    }
    #pragma unroll
    for (int o = 16; o; o >>= 1) s += __shfl_xor_sync(0xffffffffu, s, o);
    if (lane == 0) g_hid[(g << 8) + hid] = fmaxf(s + b1[hid], 0.0f);
}

// logits = hidden @ W2.T + b2: one warp per (g, class)
__global__ void k_logits(const float* __restrict__ W2, const float* __restrict__ b2,
                         float* __restrict__ out) {
    int t = blockIdx.x * blockDim.x + threadIdx.x;
    int warp = t >> 5, lane = t & 31;
    if (warp >= NGRAPH * NCLS) return;
    int g = warp / NCLS, c = warp - g * NCLS;
    const float* hr = g_hid + (g << 8);
    const float* wr = W2 + (c << 8);
    float s = 0.0f;
    #pragma unroll
    for (int k = lane; k < NHID; k += 32) s += hr[k] * wr[k];
    #pragma unroll
    for (int o = 16; o; o >>= 1) s += __shfl_xor_sync(0xffffffffu, s, o);
    if (lane == 0) out[g * NCLS + c] = s + b2[c];
}

extern "C" void kernel_launch(void* const* d_in, const int* in_sizes, int n_in,
                              void* d_out, int out_size) {
    const float* x  = (const float*)d_in[0];
    const float* nw = (const float*)d_in[1];
    const float* ew = (const float*)d_in[2];
    const float* fw = (const float*)d_in[3];
    const float* v  = (const float*)d_in[4];
    const float* W1 = (const float*)d_in[5];
    const float* b1 = (const float*)d_in[6];
    const float* W2 = (const float*)d_in[7];
    const float* b2 = (const float*)d_in[8];
    const int*   ei = (const int*)d_in[9];   // edge_index [2,E] (int32)
    const int*   fc = (const int*)d_in[10];  // face [3,F]
    const int*   bid= (const int*)d_in[11];  // batch_ids [N]

    int N = in_sizes[1];   // node_weights count
    int E = in_sizes[2];   // edge_weights count
    int F = in_sizes[3];   // face_weights count
    int M = N + E + F;

    float* out  = (float*)d_out;           // [0, 320): logits
    float* flat = out + NGRAPH * NCLS;     // [320, 320+65536): flat ECC

    k_zero<<<(NGRAPH * NBUMP * NDIR) / 256, 256>>>();
    k_count<<<SORT_BLOCKS, SORT_THREADS>>>(ei, fc, bid, E, F);
    k_offsets<<<1, 64>>>(E);
    k_scatter<<<SORT_BLOCKS, SORT_THREADS>>>(ei, fc, bid, E, F);
    k_nh<<<(N * NDIR + 255) / 256, 256>>>(x, nw, v, N);
    k_ecc<<<(M + ECC_ITEMS - 1) / ECC_ITEMS, 256>>>(ew, fw, ei, fc, bid, N, E, F);
    k_prefix<<<8, 256>>>(flat);
    k_hidden<<<1024, 256>>>(flat, W1, b1);
    k_logits<<<(NGRAPH * NCLS * 32 + 255) / 256, 256>>>(W2, b2, out);
}